// round 12
// baseline (speedup 1.0000x reference)
#include <cuda_runtime.h>
#include <cuda_bf16.h>
#include <cstdint>

#define BB 8
#define SS 4096
#define HH 1024
#define KK 2048      // K = 0.5 * S
#define NBIN 4096    // 12-bit radix bins per row

__device__ float g_scores[BB * SS];      // sigmoid(logit)
__device__ int   g_hist[BB * NBIN];      // top-12-bit bins; re-zeroed by topk

__device__ __forceinline__ uint32_t orderable(float f) {
    uint32_t u = __float_as_uint(f);
    return u ^ ((u >> 31) ? 0xFFFFFFFFu : 0x80000000u);
}

// ---------------------------------------------------------------------------
// Pass 1: router GEMV, 2 tokens/warp. Lane 0 applies sigmoid, stores scores,
// and bins the top-12-bits histogram via global red atomics (hidden under
// the DRAM-bound mainloop).
// ---------------------------------------------------------------------------
__global__ __launch_bounds__(256) void router_logits_kernel(
    const float* __restrict__ x, const float* __restrict__ w,
    float* __restrict__ scores, int* __restrict__ hist_g)
{
    int gw   = (blockIdx.x * blockDim.x + threadIdx.x) >> 5;
    int lane = threadIdx.x & 31;
    int r0   = gw * 2;
    if (r0 >= BB * SS) return;

    const float4* xp0 = reinterpret_cast<const float4*>(x + (size_t)r0 * HH);
    const float4* xp1 = xp0 + (HH / 4);
    const float4* wp  = reinterpret_cast<const float4*>(w);

    float a0 = 0.0f, a1 = 0.0f;
#pragma unroll
    for (int i = 0; i < 8; i++) {                 // 8 * 32 * 4 = 1024 = H
        int idx = lane + i * 32;
        float4 wv = __ldg(&wp[idx]);
        float4 u  = xp0[idx];
        float4 t  = xp1[idx];
        a0 = fmaf(u.x, wv.x, a0); a0 = fmaf(u.y, wv.y, a0);
        a0 = fmaf(u.z, wv.z, a0); a0 = fmaf(u.w, wv.w, a0);
        a1 = fmaf(t.x, wv.x, a1); a1 = fmaf(t.y, wv.y, a1);
        a1 = fmaf(t.z, wv.z, a1); a1 = fmaf(t.w, wv.w, a1);
    }
#pragma unroll
    for (int o = 16; o; o >>= 1) {
        a0 += __shfl_xor_sync(0xFFFFFFFFu, a0, o);
        a1 += __shfl_xor_sync(0xFFFFFFFFu, a1, o);
    }
    if (lane == 0) {
        float s0 = 1.0f / (1.0f + expf(-a0));
        float s1 = 1.0f / (1.0f + expf(-a1));
        scores[r0]     = s0;
        scores[r0 + 1] = s1;
        int* hrow = hist_g + (r0 >> 12) * NBIN;   // row = r0 / SS
        atomicAdd(&hrow[orderable(s0) >> 20], 1);
        atomicAdd(&hrow[orderable(s1) >> 20], 1);
    }
}

// ---------------------------------------------------------------------------
// Pass 2: per-row exact top-K + emit. One block (1024 thr) per row.
// Single descending block-scan over the 4096-bin hist -> 12-bit prefix,
// then exact cutoff among the (few) candidates in that bin via rank count
// on (key desc, idx asc) composites. Handles all ties exactly.
// ---------------------------------------------------------------------------
__global__ __launch_bounds__(1024) void topk_select_kernel(
    const float* __restrict__ scores, int* __restrict__ hist_g,
    float* __restrict__ out, int out_size)
{
    __shared__ int      s_wsum[32];
    __shared__ int      s_wexcl[32];
    __shared__ int      s_P;        // selected 12-bit prefix (bin index)
    __shared__ int      s_T;        // quota within the bin
    __shared__ int      s_cnt;      // candidate count
    __shared__ uint32_t s_ckey[SS]; // candidate keys   (16 KB)
    __shared__ int      s_cidx[SS]; // candidate indices(16 KB)
    __shared__ uint32_t s_cut_key;
    __shared__ int      s_cut_idx;

    const int b    = blockIdx.x;
    const int tid  = threadIdx.x;
    const int lane = tid & 31;
    const int wid  = tid >> 5;
    const float* rowp = scores + b * SS;
    int* hrow = hist_g + b * NBIN;

    // Load this thread's 4 consecutive scores; keys in registers.
    float4 lv = *reinterpret_cast<const float4*>(rowp + tid * 4);
    float    v[4] = {lv.x, lv.y, lv.z, lv.w};
    uint32_t k[4];
#pragma unroll
    for (int i = 0; i < 4; i++)
        k[i] = orderable(v[i]);

    if (tid == 0) s_cnt = 0;

    // ---- Descending block-scan over 4096 bins (4 bins/thread) ----
    // Thread t covers bins [4095-4t .. 4092-4t], descending within chunk.
    int h[4];
    int part = 0;
#pragma unroll
    for (int j = 0; j < 4; j++) {
        h[j] = hrow[NBIN - 1 - 4 * tid - j];
        part += h[j];
    }
    // Re-zero the bins we just consumed (for the next graph replay).
#pragma unroll
    for (int j = 0; j < 4; j++)
        hrow[NBIN - 1 - 4 * tid - j] = 0;

    int inc = part;
#pragma unroll
    for (int o = 1; o < 32; o <<= 1) {
        int t = __shfl_up_sync(0xFFFFFFFFu, inc, o);
        if (lane >= o) inc += t;
    }
    if (lane == 31) s_wsum[wid] = inc;
    __syncthreads();
    if (wid == 0) {
        int wv = s_wsum[lane];
        int winc = wv;
#pragma unroll
        for (int o = 1; o < 32; o <<= 1) {
            int t = __shfl_up_sync(0xFFFFFFFFu, winc, o);
            if (lane >= o) winc += t;
        }
        s_wexcl[lane] = winc - wv;
    }
    __syncthreads();

    {
        const int excl = s_wexcl[wid] + (inc - part);   // keys in higher bins
        if (excl < KK && excl + part >= KK) {           // unique crossing thread
            int acc = excl;
#pragma unroll
            for (int j = 0; j < 4; j++) {
                if (acc + h[j] >= KK) {
                    s_P = NBIN - 1 - 4 * tid - j;
                    s_T = KK - acc;
                    break;
                }
                acc += h[j];
            }
        }
    }
    __syncthreads();

    // ---- Collect candidates in the crossing bin ----
    const uint32_t P = (uint32_t)s_P;
#pragma unroll
    for (int i = 0; i < 4; i++) {
        if ((k[i] >> 20) == P) {
            int pos = atomicAdd(&s_cnt, 1);
            s_ckey[pos] = k[i];
            s_cidx[pos] = tid * 4 + i;
        }
    }
    __syncthreads();

    // ---- Exact cutoff: candidate with rank T-1 in (key desc, idx asc) ----
    const int E = s_cnt;     // >= T >= 1
    const int T = s_T;
    for (int c = tid; c < E; c += 1024) {
        uint32_t ck = s_ckey[c];
        int      ci = s_cidx[c];
        int better = 0;
        for (int e = 0; e < E; e++) {
            uint32_t ek = s_ckey[e];
            better += (ek > ck) || (ek == ck && s_cidx[e] < ci);
        }
        if (better == T - 1) {
            s_cut_key = ck;
            s_cut_idx = ci;
        }
    }
    __syncthreads();

    const uint32_t cut_key = s_cut_key;
    const int      cut_idx = s_cut_idx;

    // ---- Emit: accept iff (key,idx) >= cutoff in (key desc, idx asc) ----
    const int  base = b * SS;
    const bool has_mask_half = (out_size >= 2 * BB * SS);
    float wv4[4], mv4[4];
#pragma unroll
    for (int i = 0; i < 4; i++) {
        int s = tid * 4 + i;
        bool m = (k[i] > cut_key) || (k[i] == cut_key && s <= cut_idx);
        wv4[i] = m ? v[i] : 0.0f;
        mv4[i] = m ? 1.0f : 0.0f;
    }
    *reinterpret_cast<float4*>(out + base + tid * 4) =
        make_float4(wv4[0], wv4[1], wv4[2], wv4[3]);
    if (has_mask_half)
        *reinterpret_cast<float4*>(out + BB * SS + base + tid * 4) =
            make_float4(mv4[0], mv4[1], mv4[2], mv4[3]);
}

extern "C" void kernel_launch(void* const* d_in, const int* in_sizes, int n_in,
                              void* d_out, int out_size)
{
    const float* hidden = (const float*)d_in[0];
    const float* w      = (const float*)d_in[1];
    float* out = (float*)d_out;

    float* scores = nullptr;
    int*   hist   = nullptr;
    cudaGetSymbolAddress((void**)&scores, g_scores);
    cudaGetSymbolAddress((void**)&hist,   g_hist);

    const int tokens = BB * SS;
    router_logits_kernel<<<tokens / 16, 256>>>(hidden, w, scores, hist);
    topk_select_kernel<<<BB, 1024>>>(scores, hist, out, out_size);
}

// round 14
// speedup vs baseline: 1.9098x; 1.9098x over previous
#include <cuda_runtime.h>
#include <cuda_bf16.h>
#include <cstdint>

#define BB 8
#define SS 4096
#define HH 1024
#define KK 2048      // K = 0.5 * S
#define NBIN 4096    // uniform bins over score in (0,1)
#define MAXC 1024    // candidate buffer cap (E is ~1-6 in practice)

__device__ float g_scores[BB * SS];      // sigmoid(logit)
__device__ int   g_hist[BB * NBIN];      // uniform bins; re-zeroed by topk

__device__ __forceinline__ uint32_t orderable(float f) {
    uint32_t u = __float_as_uint(f);
    return u ^ ((u >> 31) ? 0xFFFFFFFFu : 0x80000000u);
}

// Monotone uniform bin for score in (0,1). floor(s*4096), clamped.
__device__ __forceinline__ int score_bin(float s) {
    int b = (int)(s * 4096.0f);
    return min(max(b, 0), NBIN - 1);
}

// ---------------------------------------------------------------------------
// Pass 1: router GEMV, 2 tokens/warp, streaming loads. Lane 0 applies
// sigmoid, stores scores, and bins the uniform histogram via global red
// atomics (hidden under the DRAM-bound mainloop).
// ---------------------------------------------------------------------------
__global__ __launch_bounds__(256) void router_logits_kernel(
    const float* __restrict__ x, const float* __restrict__ w,
    float* __restrict__ scores, int* __restrict__ hist_g)
{
    int gw   = (blockIdx.x * blockDim.x + threadIdx.x) >> 5;
    int lane = threadIdx.x & 31;
    int r0   = gw * 2;
    if (r0 >= BB * SS) return;

    const float4* xp0 = reinterpret_cast<const float4*>(x + (size_t)r0 * HH);
    const float4* xp1 = xp0 + (HH / 4);
    const float4* wp  = reinterpret_cast<const float4*>(w);

    float a0 = 0.0f, a1 = 0.0f;
#pragma unroll
    for (int i = 0; i < 8; i++) {                 // 8 * 32 * 4 = 1024 = H
        int idx = lane + i * 32;
        float4 wv = __ldg(&wp[idx]);
        float4 u  = __ldcs(&xp0[idx]);            // streaming: read-once data
        float4 t  = __ldcs(&xp1[idx]);
        a0 = fmaf(u.x, wv.x, a0); a0 = fmaf(u.y, wv.y, a0);
        a0 = fmaf(u.z, wv.z, a0); a0 = fmaf(u.w, wv.w, a0);
        a1 = fmaf(t.x, wv.x, a1); a1 = fmaf(t.y, wv.y, a1);
        a1 = fmaf(t.z, wv.z, a1); a1 = fmaf(t.w, wv.w, a1);
    }
#pragma unroll
    for (int o = 16; o; o >>= 1) {
        a0 += __shfl_xor_sync(0xFFFFFFFFu, a0, o);
        a1 += __shfl_xor_sync(0xFFFFFFFFu, a1, o);
    }
    if (lane == 0) {
        float s0 = 1.0f / (1.0f + expf(-a0));
        float s1 = 1.0f / (1.0f + expf(-a1));
        scores[r0]     = s0;
        scores[r0 + 1] = s1;
        int* hrow = hist_g + (r0 >> 12) * NBIN;   // row = r0 / SS
        atomicAdd(&hrow[score_bin(s0)], 1);
        atomicAdd(&hrow[score_bin(s1)], 1);
    }
}

// ---------------------------------------------------------------------------
// Pass 2: per-row exact top-K + emit. One block (1024 thr) per row.
// Single descending block-scan over 4096 UNIFORM bins -> bin P + quota T.
// Candidates sharing bin P (typically ~1-6) get an exact rank count on
// (key desc, idx asc), which also resolves ties identically to lax.top_k.
// ---------------------------------------------------------------------------
__global__ __launch_bounds__(1024) void topk_select_kernel(
    const float* __restrict__ scores, int* __restrict__ hist_g,
    float* __restrict__ out, int out_size)
{
    __shared__ int      s_wsum[32];
    __shared__ int      s_wexcl[32];
    __shared__ int      s_P;          // selected bin
    __shared__ int      s_T;          // quota within the bin
    __shared__ int      s_cnt;        // candidate count
    __shared__ uint32_t s_ckey[MAXC];
    __shared__ int      s_cidx[MAXC];
    __shared__ uint32_t s_cut_key;
    __shared__ int      s_cut_idx;

    const int b    = blockIdx.x;
    const int tid  = threadIdx.x;
    const int lane = tid & 31;
    const int wid  = tid >> 5;
    const float* rowp = scores + b * SS;
    int* hrow = hist_g + b * NBIN;

    // Load this thread's 4 consecutive scores; keys in registers.
    float4 lv = *reinterpret_cast<const float4*>(rowp + tid * 4);
    float    v[4] = {lv.x, lv.y, lv.z, lv.w};
    uint32_t k[4];
#pragma unroll
    for (int i = 0; i < 4; i++)
        k[i] = orderable(v[i]);

    if (tid == 0) s_cnt = 0;

    // ---- Descending block-scan over 4096 bins (4 bins/thread) ----
    int h[4];
    int part = 0;
#pragma unroll
    for (int j = 0; j < 4; j++) {
        h[j] = hrow[NBIN - 1 - 4 * tid - j];
        part += h[j];
    }
    // Re-zero consumed bins for the next graph replay.
#pragma unroll
    for (int j = 0; j < 4; j++)
        hrow[NBIN - 1 - 4 * tid - j] = 0;

    int inc = part;
#pragma unroll
    for (int o = 1; o < 32; o <<= 1) {
        int t = __shfl_up_sync(0xFFFFFFFFu, inc, o);
        if (lane >= o) inc += t;
    }
    if (lane == 31) s_wsum[wid] = inc;
    __syncthreads();
    if (wid == 0) {
        int wv = s_wsum[lane];
        int winc = wv;
#pragma unroll
        for (int o = 1; o < 32; o <<= 1) {
            int t = __shfl_up_sync(0xFFFFFFFFu, winc, o);
            if (lane >= o) winc += t;
        }
        s_wexcl[lane] = winc - wv;
    }
    __syncthreads();

    {
        const int excl = s_wexcl[wid] + (inc - part);   // keys in higher bins
        if (excl < KK && excl + part >= KK) {           // unique crossing thread
            int acc = excl;
#pragma unroll
            for (int j = 0; j < 4; j++) {
                if (acc + h[j] >= KK) {
                    s_P = NBIN - 1 - 4 * tid - j;
                    s_T = KK - acc;
                    break;
                }
                acc += h[j];
            }
        }
    }
    __syncthreads();

    // ---- Collect candidates in the crossing bin (uniform -> E tiny) ----
    const int P = s_P;
#pragma unroll
    for (int i = 0; i < 4; i++) {
        if (score_bin(v[i]) == P) {
            int pos = atomicAdd(&s_cnt, 1);
            if (pos < MAXC) {
                s_ckey[pos] = k[i];
                s_cidx[pos] = tid * 4 + i;
            }
        }
    }
    __syncthreads();

    // ---- Exact cutoff: candidate with rank T-1 in (key desc, idx asc) ----
    const int E = min(s_cnt, MAXC);   // == hist bin count in practice
    const int T = s_T;
    for (int c = tid; c < E; c += 1024) {
        uint32_t ck = s_ckey[c];
        int      ci = s_cidx[c];
        int better = 0;
        for (int e = 0; e < E; e++) {
            uint32_t ek = s_ckey[e];
            better += (ek > ck) || (ek == ck && s_cidx[e] < ci);
        }
        if (better == T - 1) {
            s_cut_key = ck;
            s_cut_idx = ci;
        }
    }
    __syncthreads();

    const uint32_t cut_key = s_cut_key;
    const int      cut_idx = s_cut_idx;

    // ---- Emit: accept iff (key,idx) >= cutoff in (key desc, idx asc) ----
    const int  base = b * SS;
    const bool has_mask_half = (out_size >= 2 * BB * SS);
    float wv4[4], mv4[4];
#pragma unroll
    for (int i = 0; i < 4; i++) {
        int s = tid * 4 + i;
        bool m = (k[i] > cut_key) || (k[i] == cut_key && s <= cut_idx);
        wv4[i] = m ? v[i] : 0.0f;
        mv4[i] = m ? 1.0f : 0.0f;
    }
    *reinterpret_cast<float4*>(out + base + tid * 4) =
        make_float4(wv4[0], wv4[1], wv4[2], wv4[3]);
    if (has_mask_half)
        *reinterpret_cast<float4*>(out + BB * SS + base + tid * 4) =
            make_float4(mv4[0], mv4[1], mv4[2], mv4[3]);
}

extern "C" void kernel_launch(void* const* d_in, const int* in_sizes, int n_in,
                              void* d_out, int out_size)
{
    const float* hidden = (const float*)d_in[0];
    const float* w      = (const float*)d_in[1];
    float* out = (float*)d_out;

    float* scores = nullptr;
    int*   hist   = nullptr;
    cudaGetSymbolAddress((void**)&scores, g_scores);
    cudaGetSymbolAddress((void**)&hist,   g_hist);

    const int tokens = BB * SS;
    router_logits_kernel<<<tokens / 16, 256>>>(hidden, w, scores, hist);
    topk_select_kernel<<<BB, 1024>>>(scores, hist, out, out_size);
}